// round 11
// baseline (speedup 1.0000x reference)
#include <cuda_runtime.h>
#include <cuda_bf16.h>
#include <cuda_fp16.h>
#include <mma.h>
#include <cstdint>

using namespace nvcuda;

#define B_ 8
#define T_ 256
#define S_ 400
#define H_ 512
#define V_ 32000
#define R_ 2048   // B*T rows

// ---- scratch (no cudaMalloc allowed -> __device__ globals) ----
__device__ __half          g_exph[(size_t)R_ * V_];   // 131 MB: exp(logits) fp16
__device__ __nv_bfloat16   g_w2t[(size_t)V_ * H_];    // 32.8 MB: w2 transposed [V][H] bf16
__device__ __nv_bfloat16   g_hidden[R_ * H_];         // 2 MB: bf16 hidden
__device__ float           g_pgen[R_];
__device__ float           g_rowsum[R_];

// ---- cp.async helpers ----
__device__ __forceinline__ uint32_t smem_u32(const void* p) {
    uint32_t a;
    asm("{ .reg .u64 t; cvta.to.shared.u64 t, %1; cvt.u32.u64 %0, t; }" : "=r"(a) : "l"(p));
    return a;
}
__device__ __forceinline__ void cp16(uint32_t dst, const void* src) {
    asm volatile("cp.async.cg.shared.global [%0], [%1], 16;" :: "r"(dst), "l"(src));
}
__device__ __forceinline__ void cp_commit() { asm volatile("cp.async.commit_group;"); }
__device__ __forceinline__ void cp_wait1() { asm volatile("cp.async.wait_group 1;" ::: "memory"); }
__device__ __forceinline__ void cp_wait0() { asm volatile("cp.async.wait_group 0;" ::: "memory"); }

// ===========================================================================
// K1: p_gen = sigmoid(state_input @ w_pgen + b_pgen); zero row sums.
// ===========================================================================
__global__ void pgen_kernel(const float* __restrict__ state,
                            const float* __restrict__ wp,
                            const float* __restrict__ bp) {
    int row  = blockIdx.x * 8 + (threadIdx.x >> 5);
    int lane = threadIdx.x & 31;
    const float* x = state + (size_t)row * (2 * H_);
    float s = 0.f;
    #pragma unroll 8
    for (int i = lane; i < 2 * H_; i += 32) s += x[i] * wp[i];
    #pragma unroll
    for (int o = 16; o; o >>= 1) s += __shfl_xor_sync(0xffffffffu, s, o);
    if (lane == 0) {
        float z = s + bp[0];
        g_pgen[row]   = 1.f / (1.f + __expf(-z));
        g_rowsum[row] = 0.f;
    }
}

// ===========================================================================
// K2: transpose w2 [H][V] fp32 -> g_w2t [V][H] bf16 (K-major B for the GEMM)
// ===========================================================================
__global__ void transpose_w2_kernel(const float* __restrict__ w2) {
    __shared__ float tile[32][33];
    int c0 = blockIdx.x * 32;   // vocab base
    int r0 = blockIdx.y * 32;   // H base
    int tx = threadIdx.x & 31, ty = threadIdx.x >> 5;  // 32 x 8
    #pragma unroll
    for (int i = 0; i < 4; i++)
        tile[ty + i * 8][tx] = w2[(size_t)(r0 + ty + i * 8) * V_ + c0 + tx];
    __syncthreads();
    #pragma unroll
    for (int i = 0; i < 4; i++)
        g_w2t[(size_t)(c0 + ty + i * 8) * H_ + r0 + tx] =
            __float2bfloat16(tile[tx][ty + i * 8]);
}

// ===========================================================================
// K3: hidden = s_output @ w1 + b1  (2048x512x512) -- WMMA bf16, fp32 accum.
// ===========================================================================
#define HLD 72
__global__ void __launch_bounds__(128)
hidden_wmma_kernel(const float* __restrict__ A,
                   const float* __restrict__ W,
                   const float* __restrict__ b1) {
    __shared__ __nv_bfloat16 As[64 * HLD];
    __shared__ __nv_bfloat16 Bs[64 * HLD];
    int tid = threadIdx.x, wid = tid >> 5, lane = tid & 31;
    int warpM = wid >> 1, warpN = wid & 1;
    int m0 = blockIdx.y * 64, n0 = blockIdx.x * 64;

    wmma::fragment<wmma::accumulator, 16, 16, 16, float> c[2][2];
    #pragma unroll
    for (int i = 0; i < 2; i++)
        #pragma unroll
        for (int j = 0; j < 2; j++) wmma::fill_fragment(c[i][j], 0.f);

    for (int kc = 0; kc < 8; kc++) {
        __syncthreads();
        #pragma unroll
        for (int h = 0; h < 8; h++) {
            int idx = tid + h * 128;          // 0..1023 float4 slots
            int r = idx >> 4, c4 = idx & 15;
            float4 v = *(const float4*)&A[(size_t)(m0 + r) * H_ + kc * 64 + c4 * 4];
            __nv_bfloat162* d2 = (__nv_bfloat162*)&As[r * HLD + c4 * 4];
            d2[0] = __floats2bfloat162_rn(v.x, v.y);
            d2[1] = __floats2bfloat162_rn(v.z, v.w);
        }
        #pragma unroll
        for (int h = 0; h < 8; h++) {
            int idx = tid + h * 128;
            int r = idx >> 4, c4 = idx & 15;
            float4 v = *(const float4*)&W[(size_t)(kc * 64 + r) * H_ + n0 + c4 * 4];
            __nv_bfloat162* d2 = (__nv_bfloat162*)&Bs[r * HLD + c4 * 4];
            d2[0] = __floats2bfloat162_rn(v.x, v.y);
            d2[1] = __floats2bfloat162_rn(v.z, v.w);
        }
        __syncthreads();
        #pragma unroll
        for (int kf = 0; kf < 4; kf++) {
            wmma::fragment<wmma::matrix_a, 16, 16, 16, __nv_bfloat16, wmma::row_major> a[2];
            wmma::fragment<wmma::matrix_b, 16, 16, 16, __nv_bfloat16, wmma::row_major> b[2];
            #pragma unroll
            for (int i = 0; i < 2; i++)
                wmma::load_matrix_sync(a[i], As + (warpM * 32 + i * 16) * HLD + kf * 16, HLD);
            #pragma unroll
            for (int j = 0; j < 2; j++)
                wmma::load_matrix_sync(b[j], Bs + (kf * 16) * HLD + warpN * 32 + j * 16, HLD);
            #pragma unroll
            for (int i = 0; i < 2; i++)
                #pragma unroll
                for (int j = 0; j < 2; j++)
                    wmma::mma_sync(c[i][j], a[i], b[j], c[i][j]);
        }
    }
    __syncthreads();
    float* buf = (float*)As + wid * 320;      // 16x20 per-warp staging
    int r = lane >> 1, cbase = (lane & 1) * 8;
    #pragma unroll
    for (int i = 0; i < 2; i++)
        #pragma unroll
        for (int j = 0; j < 2; j++) {
            wmma::store_matrix_sync(buf, c[i][j], 20, wmma::mem_row_major);
            __syncwarp();
            int row = m0 + warpM * 32 + i * 16 + r;
            int col = n0 + warpN * 32 + j * 16 + cbase;
            union { __nv_bfloat162 b2v[4]; uint4 u4; } uu;
            #pragma unroll
            for (int k2 = 0; k2 < 4; k2++)
                uu.b2v[k2] = __floats2bfloat162_rn(
                    buf[r * 20 + cbase + 2 * k2]     + b1[col + 2 * k2],
                    buf[r * 20 + cbase + 2 * k2 + 1] + b1[col + 2 * k2 + 1]);
            *(uint4*)&g_hidden[(size_t)row * H_ + col] = uu.u4;
            __syncwarp();
        }
}

// ===========================================================================
// K4: WMMA GEMM (2048 x 32000 x 512, bf16, fp32 accum) + fused epilogue.
// CTA tile 128(M)x256(N), BK=64, 3-stage cp.async ring, 8 warps (2Mx4N),
// warp tile 64x64: per kf-step 8 LDSM feed 16 WMMA (2x density vs 64x32).
// ld = 72 elements -> conflict-free ldmatrix.
// ===========================================================================
#define LDP   72
#define ACH   (128 * LDP * 2)          // 18432 B per A stage
#define BCH   (256 * LDP * 2)          // 36864 B per B stage
#define SM_A  0                        // 3 A stages
#define SM_B  (3 * ACH)                // 3 B stages
#define GSMEM (3 * ACH + 3 * BCH)      // 165888 B

__global__ void __launch_bounds__(256, 1)
logits_wmma_kernel(const float* __restrict__ b2) {
    extern __shared__ char sm[];
    uint32_t sb = smem_u32(sm);
    float* stage = (float*)sm;                   // epilogue reuse of stage 0
    float* rowsum_sm = (float*)(sm + 10240);

    int tid = threadIdx.x, wid = tid >> 5, lane = tid & 31;
    int warpM = wid >> 2, warpN = wid & 3;
    int n0 = blockIdx.x * 256, m0 = blockIdx.y * 128;

    wmma::fragment<wmma::accumulator, 16, 16, 16, float> c[4][4];
    #pragma unroll
    for (int i = 0; i < 4; i++)
        #pragma unroll
        for (int j = 0; j < 4; j++) wmma::fill_fragment(c[i][j], 0.f);

    auto load_chunk = [&](int kc, int buf) {
        #pragma unroll
        for (int h = 0; h < 4; h++) {
            int idx = tid + h * 256;             // 0..1023 (128 rows x 8 x16B)
            int r = idx >> 3, c16 = idx & 7;
            cp16(sb + SM_A + buf * ACH + r * (LDP * 2) + c16 * 16,
                 &g_hidden[(size_t)(m0 + r) * H_ + kc * 64 + c16 * 8]);
        }
        #pragma unroll
        for (int h = 0; h < 8; h++) {
            int idx = tid + h * 256;             // 0..2047 (256 rows x 8 x16B)
            int r = idx >> 3, c16 = idx & 7;
            cp16(sb + SM_B + buf * BCH + r * (LDP * 2) + c16 * 16,
                 &g_w2t[(size_t)(n0 + r) * H_ + kc * 64 + c16 * 8]);
        }
        cp_commit();
    };

    load_chunk(0, 0);
    load_chunk(1, 1);

    const __nv_bfloat16* Asm = (const __nv_bfloat16*)(sm + SM_A);
    const __nv_bfloat16* Bsm = (const __nv_bfloat16*)(sm + SM_B);

    for (int kc = 0; kc < 8; kc++) {
        if (kc == 7) cp_wait0(); else cp_wait1();   // chunk kc resident
        __syncthreads();                            // data visible; prev compute done
        if (kc + 2 < 8) load_chunk(kc + 2, (kc + 2) % 3);

        int buf = kc % 3;
        const __nv_bfloat16* Ab = Asm + buf * (ACH / 2);
        const __nv_bfloat16* Bb = Bsm + buf * (BCH / 2);
        #pragma unroll
        for (int kf = 0; kf < 4; kf++) {
            wmma::fragment<wmma::matrix_a, 16, 16, 16, __nv_bfloat16, wmma::row_major> a[4];
            wmma::fragment<wmma::matrix_b, 16, 16, 16, __nv_bfloat16, wmma::col_major> b[4];
            #pragma unroll
            for (int i = 0; i < 4; i++)
                wmma::load_matrix_sync(a[i], Ab + (warpM * 64 + i * 16) * LDP + kf * 16, LDP);
            #pragma unroll
            for (int j = 0; j < 4; j++)
                wmma::load_matrix_sync(b[j], Bb + (warpN * 64 + j * 16) * LDP + kf * 16, LDP);
            #pragma unroll
            for (int i = 0; i < 4; i++)
                #pragma unroll
                for (int j = 0; j < 4; j++)
                    wmma::mma_sync(c[i][j], a[i], b[j], c[i][j]);
        }
    }

    // ---- epilogue: exp(logit + b2) -> fp16 scratch (streaming) + row sums ----
    __syncthreads();
    if (tid < 128) rowsum_sm[tid] = 0.f;
    __syncthreads();

    float* buf = stage + wid * 320;  // 16x20 staging per warp
    int r = lane >> 1;
    int cbase = (lane & 1) * 8;
    #pragma unroll
    for (int i = 0; i < 4; i++) {
        float srow = 0.f;
        #pragma unroll
        for (int j = 0; j < 4; j++) {
            wmma::store_matrix_sync(buf, c[i][j], 20, wmma::mem_row_major);
            __syncwarp();
            int lrow = warpM * 64 + i * 16 + r;
            int grow = m0 + lrow;
            int gcol = n0 + warpN * 64 + j * 16 + cbase;
            float s = 0.f;
            union { __half2 h2[4]; uint4 u4; } uu;
            #pragma unroll
            for (int k2 = 0; k2 < 4; k2++) {
                float e0 = __expf(buf[r * 20 + cbase + 2 * k2]     + __ldg(&b2[gcol + 2 * k2]));
                float e1 = __expf(buf[r * 20 + cbase + 2 * k2 + 1] + __ldg(&b2[gcol + 2 * k2 + 1]));
                s += e0 + e1;
                uu.h2[k2] = __floats2half2_rn(e0, e1);
            }
            __stcs((uint4*)&g_exph[(size_t)grow * V_ + gcol], uu.u4);
            srow += s;
            __syncwarp();
        }
        int lrow = warpM * 64 + i * 16 + r;
        srow += __shfl_xor_sync(0xffffffffu, srow, 1);
        if ((lane & 1) == 0) atomicAdd(&rowsum_sm[lrow], srow);
    }
    __syncthreads();
    if (tid < 128) atomicAdd(&g_rowsum[m0 + tid], rowsum_sm[tid]);
}

// ===========================================================================
// K5: out = log(p*exph/sum + (1-p)*scatter(attn) + 1e-12)
// ===========================================================================
__device__ __forceinline__ float hash_lookup(int idx, const int* keys, const float* vals) {
    int h = idx & 1023;
    while (keys[h] != idx) h = (h + 1) & 1023;
    return vals[h];
}

__global__ void final_kernel(const float* __restrict__ attn,
                             const int* __restrict__ ebev,
                             float* __restrict__ out) {
    __shared__ unsigned bitmap[1000];
    __shared__ int keys[1024];
    __shared__ float vals[1024];
    int row = blockIdx.x;
    int b = row >> 8;
    int tid = threadIdx.x;
    for (int i = tid; i < 1000; i += 256) bitmap[i] = 0u;
    for (int i = tid; i < 1024; i += 256) { keys[i] = -1; vals[i] = 0.f; }
    __syncthreads();
    float p = g_pgen[row];
    float omp = 1.f - p;
    float scale = p / g_rowsum[row];
    for (int s = tid; s < S_; s += 256) {
        int idx = ebev[b * S_ + s];
        float v = omp * attn[(size_t)row * S_ + s];
        atomicOr(&bitmap[idx >> 5], 1u << (idx & 31));
        int h = idx & 1023;
        while (true) {
            int old = atomicCAS(&keys[h], -1, idx);
            if (old == -1 || old == idx) { atomicAdd(&vals[h], v); break; }
            h = (h + 1) & 1023;
        }
    }
    __syncthreads();
    const uint4* erow = (const uint4*)&g_exph[(size_t)row * V_];
    float4* orow = (float4*)&out[(size_t)row * V_];
    for (int q = tid; q < V_ / 8; q += 256) {
        uint4 e8 = __ldcs(&erow[q]);
        int vbase = q * 8;
        unsigned w = (bitmap[vbase >> 5] >> (vbase & 31)) & 0xFFu;
        const __half2* hp = (const __half2*)&e8;
        float f[8];
        #pragma unroll
        for (int k = 0; k < 4; k++) {
            float2 fv = __half22float2(hp[k]);
            f[2 * k]     = fv.x * scale + 1e-12f;
            f[2 * k + 1] = fv.y * scale + 1e-12f;
        }
        if (w) {
            #pragma unroll
            for (int k = 0; k < 8; k++)
                if (w & (1u << k)) f[k] += hash_lookup(vbase + k, keys, vals);
        }
        __stcs(&orow[2 * q],     make_float4(__logf(f[0]), __logf(f[1]), __logf(f[2]), __logf(f[3])));
        __stcs(&orow[2 * q + 1], make_float4(__logf(f[4]), __logf(f[5]), __logf(f[6]), __logf(f[7])));
    }
}

// ===========================================================================
extern "C" void kernel_launch(void* const* d_in, const int* in_sizes, int n_in,
                              void* d_out, int out_size) {
    const float* s_output = (const float*)d_in[0];
    const float* state    = (const float*)d_in[1];
    const float* attn     = (const float*)d_in[2];
    const int*   ebev     = (const int*)d_in[3];
    const float* w_pgen   = (const float*)d_in[4];
    const float* b_pgen   = (const float*)d_in[5];
    const float* w1       = (const float*)d_in[6];
    const float* b1       = (const float*)d_in[7];
    const float* w2       = (const float*)d_in[8];
    const float* b2       = (const float*)d_in[9];
    float* out = (float*)d_out;

    cudaFuncSetAttribute(logits_wmma_kernel,
                         cudaFuncAttributeMaxDynamicSharedMemorySize, GSMEM);

    pgen_kernel<<<R_ / 8, 256>>>(state, w_pgen, b_pgen);
    transpose_w2_kernel<<<dim3(V_ / 32, H_ / 32), 256>>>(w2);
    hidden_wmma_kernel<<<dim3(H_ / 64, R_ / 64), 128>>>(s_output, w1, b1);
    logits_wmma_kernel<<<dim3(V_ / 256, R_ / 128), 256, GSMEM>>>(b2);
    final_kernel<<<R_, 256>>>(attn, ebev, out);
}

// round 12
// speedup vs baseline: 1.0109x; 1.0109x over previous
#include <cuda_runtime.h>
#include <cuda_bf16.h>
#include <cuda_fp16.h>
#include <mma.h>
#include <cstdint>

using namespace nvcuda;

#define B_ 8
#define T_ 256
#define S_ 400
#define H_ 512
#define V_ 32000
#define R_ 2048   // B*T rows

// ---- scratch (no cudaMalloc allowed -> __device__ globals) ----
__device__ __half          g_logit[(size_t)R_ * V_]; // 131 MB: logits+b2 fp16
__device__ __nv_bfloat16   g_w2t[(size_t)V_ * H_];   // 32.8 MB: w2 transposed [V][H] bf16
__device__ __nv_bfloat16   g_hidden[R_ * H_];        // 2 MB: bf16 hidden
__device__ float           g_pgen[R_];
__device__ float           g_rowsum[R_];

// ---- cp.async helpers ----
__device__ __forceinline__ uint32_t smem_u32(const void* p) {
    uint32_t a;
    asm("{ .reg .u64 t; cvta.to.shared.u64 t, %1; cvt.u32.u64 %0, t; }" : "=r"(a) : "l"(p));
    return a;
}
__device__ __forceinline__ void cp16(uint32_t dst, const void* src) {
    asm volatile("cp.async.cg.shared.global [%0], [%1], 16;" :: "r"(dst), "l"(src));
}
__device__ __forceinline__ void cp_commit() { asm volatile("cp.async.commit_group;"); }
__device__ __forceinline__ void cp_wait1() { asm volatile("cp.async.wait_group 1;" ::: "memory"); }
__device__ __forceinline__ void cp_wait0() { asm volatile("cp.async.wait_group 0;" ::: "memory"); }

// ===========================================================================
// K1: p_gen = sigmoid(state_input @ w_pgen + b_pgen); zero row sums.
// ===========================================================================
__global__ void pgen_kernel(const float* __restrict__ state,
                            const float* __restrict__ wp,
                            const float* __restrict__ bp) {
    int row  = blockIdx.x * 8 + (threadIdx.x >> 5);
    int lane = threadIdx.x & 31;
    const float* x = state + (size_t)row * (2 * H_);
    float s = 0.f;
    #pragma unroll 8
    for (int i = lane; i < 2 * H_; i += 32) s += x[i] * wp[i];
    #pragma unroll
    for (int o = 16; o; o >>= 1) s += __shfl_xor_sync(0xffffffffu, s, o);
    if (lane == 0) {
        float z = s + bp[0];
        g_pgen[row]   = 1.f / (1.f + __expf(-z));
        g_rowsum[row] = 0.f;
    }
}

// ===========================================================================
// K2: transpose w2 [H][V] fp32 -> g_w2t [V][H] bf16 (K-major B for the GEMM)
// ===========================================================================
__global__ void transpose_w2_kernel(const float* __restrict__ w2) {
    __shared__ float tile[32][33];
    int c0 = blockIdx.x * 32;   // vocab base
    int r0 = blockIdx.y * 32;   // H base
    int tx = threadIdx.x & 31, ty = threadIdx.x >> 5;  // 32 x 8
    #pragma unroll
    for (int i = 0; i < 4; i++)
        tile[ty + i * 8][tx] = w2[(size_t)(r0 + ty + i * 8) * V_ + c0 + tx];
    __syncthreads();
    #pragma unroll
    for (int i = 0; i < 4; i++)
        g_w2t[(size_t)(c0 + ty + i * 8) * H_ + r0 + tx] =
            __float2bfloat16(tile[tx][ty + i * 8]);
}

// ===========================================================================
// K3: hidden = s_output @ w1 + b1  (2048x512x512) -- WMMA bf16, fp32 accum.
// ===========================================================================
#define HLD 72
__global__ void __launch_bounds__(128)
hidden_wmma_kernel(const float* __restrict__ A,
                   const float* __restrict__ W,
                   const float* __restrict__ b1) {
    __shared__ __nv_bfloat16 As[64 * HLD];
    __shared__ __nv_bfloat16 Bs[64 * HLD];
    int tid = threadIdx.x, wid = tid >> 5, lane = tid & 31;
    int warpM = wid >> 1, warpN = wid & 1;
    int m0 = blockIdx.y * 64, n0 = blockIdx.x * 64;

    wmma::fragment<wmma::accumulator, 16, 16, 16, float> c[2][2];
    #pragma unroll
    for (int i = 0; i < 2; i++)
        #pragma unroll
        for (int j = 0; j < 2; j++) wmma::fill_fragment(c[i][j], 0.f);

    for (int kc = 0; kc < 8; kc++) {
        __syncthreads();
        #pragma unroll
        for (int h = 0; h < 8; h++) {
            int idx = tid + h * 128;          // 0..1023 float4 slots
            int r = idx >> 4, c4 = idx & 15;
            float4 v = *(const float4*)&A[(size_t)(m0 + r) * H_ + kc * 64 + c4 * 4];
            __nv_bfloat162* d2 = (__nv_bfloat162*)&As[r * HLD + c4 * 4];
            d2[0] = __floats2bfloat162_rn(v.x, v.y);
            d2[1] = __floats2bfloat162_rn(v.z, v.w);
        }
        #pragma unroll
        for (int h = 0; h < 8; h++) {
            int idx = tid + h * 128;
            int r = idx >> 4, c4 = idx & 15;
            float4 v = *(const float4*)&W[(size_t)(kc * 64 + r) * H_ + n0 + c4 * 4];
            __nv_bfloat162* d2 = (__nv_bfloat162*)&Bs[r * HLD + c4 * 4];
            d2[0] = __floats2bfloat162_rn(v.x, v.y);
            d2[1] = __floats2bfloat162_rn(v.z, v.w);
        }
        __syncthreads();
        #pragma unroll
        for (int kf = 0; kf < 4; kf++) {
            wmma::fragment<wmma::matrix_a, 16, 16, 16, __nv_bfloat16, wmma::row_major> a[2];
            wmma::fragment<wmma::matrix_b, 16, 16, 16, __nv_bfloat16, wmma::row_major> b[2];
            #pragma unroll
            for (int i = 0; i < 2; i++)
                wmma::load_matrix_sync(a[i], As + (warpM * 32 + i * 16) * HLD + kf * 16, HLD);
            #pragma unroll
            for (int j = 0; j < 2; j++)
                wmma::load_matrix_sync(b[j], Bs + (kf * 16) * HLD + warpN * 32 + j * 16, HLD);
            #pragma unroll
            for (int i = 0; i < 2; i++)
                #pragma unroll
                for (int j = 0; j < 2; j++)
                    wmma::mma_sync(c[i][j], a[i], b[j], c[i][j]);
        }
    }
    __syncthreads();
    float* buf = (float*)As + wid * 320;      // 16x20 per-warp staging
    int r = lane >> 1, cbase = (lane & 1) * 8;
    #pragma unroll
    for (int i = 0; i < 2; i++)
        #pragma unroll
        for (int j = 0; j < 2; j++) {
            wmma::store_matrix_sync(buf, c[i][j], 20, wmma::mem_row_major);
            __syncwarp();
            int row = m0 + warpM * 32 + i * 16 + r;
            int col = n0 + warpN * 32 + j * 16 + cbase;
            union { __nv_bfloat162 b2v[4]; uint4 u4; } uu;
            #pragma unroll
            for (int k2 = 0; k2 < 4; k2++)
                uu.b2v[k2] = __floats2bfloat162_rn(
                    buf[r * 20 + cbase + 2 * k2]     + b1[col + 2 * k2],
                    buf[r * 20 + cbase + 2 * k2 + 1] + b1[col + 2 * k2 + 1]);
            *(uint4*)&g_hidden[(size_t)row * H_ + col] = uu.u4;
            __syncwarp();
        }
}

// ===========================================================================
// K4: WMMA GEMM (2048 x 32000 x 512, bf16, fp32 accum) + fused epilogue:
//     l = logit + b2 -> g_logit (fp16, streaming); Z += exp(l) (fp32).
// CTA tile 128x128, BK=64, cp.async double-buffered (R6 measured-best
// structure), 8 warps (2Mx4N), warp tile 64x32, ld=72 (conflict-free).
// ===========================================================================
#define LDP  72
#define CHB  (128 * LDP * 2)          // 18432 B per tile buffer
#define SM_A 0                        // 2 buffers: A0, A1
#define SM_B (2 * CHB)                // 2 buffers: B0, B1
#define GSMEM (4 * CHB)               // 73728 B

__global__ void __launch_bounds__(256, 2)
logits_wmma_kernel(const float* __restrict__ b2) {
    extern __shared__ char sm[];
    uint32_t sb = smem_u32(sm);
    float* stage = (float*)sm;                   // epilogue reuse of A buffers
    float* rowsum_sm = (float*)(sm + 10240);     // still inside A buffer 0

    int tid = threadIdx.x, wid = tid >> 5, lane = tid & 31;
    int warpM = wid >> 2, warpN = wid & 3;
    int n0 = blockIdx.x * 128, m0 = blockIdx.y * 128;

    wmma::fragment<wmma::accumulator, 16, 16, 16, float> c[4][2];
    #pragma unroll
    for (int i = 0; i < 4; i++)
        #pragma unroll
        for (int j = 0; j < 2; j++) wmma::fill_fragment(c[i][j], 0.f);

    auto load_chunk = [&](int kc, int buf) {
        #pragma unroll
        for (int h = 0; h < 4; h++) {
            int idx = tid + h * 256;             // 0..1023
            int r = idx >> 3, c16 = idx & 7;
            cp16(sb + SM_A + buf * CHB + r * (LDP * 2) + c16 * 16,
                 &g_hidden[(size_t)(m0 + r) * H_ + kc * 64 + c16 * 8]);
        }
        #pragma unroll
        for (int h = 0; h < 4; h++) {
            int idx = tid + h * 256;
            int r = idx >> 3, c16 = idx & 7;
            cp16(sb + SM_B + buf * CHB + r * (LDP * 2) + c16 * 16,
                 &g_w2t[(size_t)(n0 + r) * H_ + kc * 64 + c16 * 8]);
        }
        cp_commit();
    };

    load_chunk(0, 0);
    load_chunk(1, 1);

    const __nv_bfloat16* Asm = (const __nv_bfloat16*)(sm + SM_A);
    const __nv_bfloat16* Bsm = (const __nv_bfloat16*)(sm + SM_B);

    for (int kc = 0; kc < 8; kc++) {
        int buf = kc & 1;
        if (kc == 7) cp_wait0(); else cp_wait1();
        __syncthreads();

        const __nv_bfloat16* Ab = Asm + buf * (CHB / 2);
        const __nv_bfloat16* Bb = Bsm + buf * (CHB / 2);
        #pragma unroll
        for (int kf = 0; kf < 4; kf++) {
            wmma::fragment<wmma::matrix_a, 16, 16, 16, __nv_bfloat16, wmma::row_major> a[4];
            #pragma unroll
            for (int i = 0; i < 4; i++)
                wmma::load_matrix_sync(a[i], Ab + (warpM * 64 + i * 16) * LDP + kf * 16, LDP);
            #pragma unroll
            for (int j = 0; j < 2; j++) {
                wmma::fragment<wmma::matrix_b, 16, 16, 16, __nv_bfloat16, wmma::col_major> bfr;
                wmma::load_matrix_sync(bfr, Bb + (warpN * 32 + j * 16) * LDP + kf * 16, LDP);
                #pragma unroll
                for (int i = 0; i < 4; i++)
                    wmma::mma_sync(c[i][j], a[i], bfr, c[i][j]);
            }
        }
        __syncthreads();
        if (kc + 2 < 8) load_chunk(kc + 2, buf);   // buffer now free
    }

    // ---- epilogue: l = logit + b2 -> fp16 scratch; rowsum Z += exp(l) ----
    __syncthreads();
    if (tid < 128) rowsum_sm[tid] = 0.f;
    __syncthreads();

    float* buf = stage + wid * 320;  // 16x20 staging per warp
    int r = lane >> 1;
    int cbase = (lane & 1) * 8;
    #pragma unroll
    for (int i = 0; i < 4; i++) {
        #pragma unroll
        for (int j = 0; j < 2; j++) {
            wmma::store_matrix_sync(buf, c[i][j], 20, wmma::mem_row_major);
            __syncwarp();
            int lrow = warpM * 64 + i * 16 + r;
            int grow = m0 + lrow;
            int gcol = n0 + warpN * 32 + j * 16 + cbase;
            float s = 0.f;
            union { __half2 h2[4]; uint4 u4; } uu;
            #pragma unroll
            for (int k2 = 0; k2 < 4; k2++) {
                float l0 = buf[r * 20 + cbase + 2 * k2]     + __ldg(&b2[gcol + 2 * k2]);
                float l1 = buf[r * 20 + cbase + 2 * k2 + 1] + __ldg(&b2[gcol + 2 * k2 + 1]);
                s += __expf(l0) + __expf(l1);
                uu.h2[k2] = __floats2half2_rn(l0, l1);
            }
            __stcs((uint4*)&g_logit[(size_t)grow * V_ + gcol], uu.u4);
            s += __shfl_xor_sync(0xffffffffu, s, 1);
            if ((lane & 1) == 0) atomicAdd(&rowsum_sm[lrow], s);
            __syncwarp();
        }
    }
    __syncthreads();
    if (tid < 128) atomicAdd(&g_rowsum[m0 + tid], rowsum_sm[tid]);
}

// ===========================================================================
// K5: out[v] = l_v + (log p - log Z)  for non-scattered v (pure linear pass);
//     scattered v (<=400/row): out[v] = log(p*exp(l_v)/Z + a_v + 1e-12)
//     via smem hash + fixup overwrite. No MUFU in the streaming loop.
// ===========================================================================
__global__ void final_kernel(const float* __restrict__ attn,
                             const int* __restrict__ ebev,
                             float* __restrict__ out) {
    __shared__ int keys[1024];
    __shared__ float vals[1024];
    int row = blockIdx.x;
    int b = row >> 8;                   // T_ = 256
    int tid = threadIdx.x;
    for (int i = tid; i < 1024; i += 256) { keys[i] = -1; vals[i] = 0.f; }
    __syncthreads();
    float p = g_pgen[row];
    float Z = g_rowsum[row];
    float omp = 1.f - p;
    float C = __logf(p) - __logf(Z);    // log(p/Z)
    float pz = p / Z;

    // build scatter hash
    for (int s = tid; s < S_; s += 256) {
        int idx = ebev[b * S_ + s];
        float v = omp * attn[(size_t)row * S_ + s];
        int h = idx & 1023;
        while (true) {
            int old = atomicCAS(&keys[h], -1, idx);
            if (old == -1 || old == idx) { atomicAdd(&vals[h], v); break; }
            h = (h + 1) & 1023;
        }
    }
    __syncthreads();

    // linear streaming pass: out = l + C
    const uint4* lrow = (const uint4*)&g_logit[(size_t)row * V_];
    float4* orow = (float4*)&out[(size_t)row * V_];
    for (int q = tid; q < V_ / 8; q += 256) {
        uint4 e8 = __ldcs(&lrow[q]);
        const __half2* hp = (const __half2*)&e8;
        float2 f0 = __half22float2(hp[0]);
        float2 f1 = __half22float2(hp[1]);
        float2 f2 = __half22float2(hp[2]);
        float2 f3 = __half22float2(hp[3]);
        __stcs(&orow[2 * q],     make_float4(f0.x + C, f0.y + C, f1.x + C, f1.y + C));
        __stcs(&orow[2 * q + 1], make_float4(f2.x + C, f2.y + C, f3.x + C, f3.y + C));
    }
    __syncthreads();

    // fixup pass: overwrite scattered entries
    for (int h = tid; h < 1024; h += 256) {
        int idx = keys[h];
        if (idx >= 0) {
            float l = __half2float(g_logit[(size_t)row * V_ + idx]);
            out[(size_t)row * V_ + idx] =
                __logf(pz * __expf(l) + vals[h] + 1e-12f);
        }
    }
}

// ===========================================================================
extern "C" void kernel_launch(void* const* d_in, const int* in_sizes, int n_in,
                              void* d_out, int out_size) {
    const float* s_output = (const float*)d_in[0];
    const float* state    = (const float*)d_in[1];
    const float* attn     = (const float*)d_in[2];
    const int*   ebev     = (const int*)d_in[3];
    const float* w_pgen   = (const float*)d_in[4];
    const float* b_pgen   = (const float*)d_in[5];
    const float* w1       = (const float*)d_in[6];
    const float* b1       = (const float*)d_in[7];
    const float* w2       = (const float*)d_in[8];
    const float* b2       = (const float*)d_in[9];
    float* out = (float*)d_out;

    cudaFuncSetAttribute(logits_wmma_kernel,
                         cudaFuncAttributeMaxDynamicSharedMemorySize, GSMEM);

    pgen_kernel<<<R_ / 8, 256>>>(state, w_pgen, b_pgen);
    transpose_w2_kernel<<<dim3(V_ / 32, H_ / 32), 256>>>(w2);
    hidden_wmma_kernel<<<dim3(H_ / 64, R_ / 64), 128>>>(s_output, w1, b1);
    logits_wmma_kernel<<<dim3(V_ / 128, R_ / 128), 256, GSMEM>>>(b2);
    final_kernel<<<R_, 256>>>(attn, ebev, out);
}

// round 14
// speedup vs baseline: 1.0992x; 1.0873x over previous
#include <cuda_runtime.h>
#include <cuda_bf16.h>
#include <cuda_fp16.h>
#include <mma.h>
#include <cstdint>

using namespace nvcuda;

#define B_ 8
#define T_ 256
#define S_ 400
#define H_ 512
#define V_ 32000
#define R_ 2048   // B*T rows

// ---- scratch (no cudaMalloc allowed -> __device__ globals) ----
__device__ __half          g_logit[(size_t)R_ * V_]; // 131 MB: logits+b2 fp16
__device__ __nv_bfloat16   g_w2t[(size_t)V_ * H_];   // 32.8 MB: w2 transposed [V][H] bf16
__device__ __nv_bfloat16   g_hidden[R_ * H_];        // 2 MB: bf16 hidden
__device__ float           g_pgen[R_];
__device__ float           g_rowsum[R_];

// ---- cp.async helpers ----
__device__ __forceinline__ uint32_t smem_u32(const void* p) {
    uint32_t a;
    asm("{ .reg .u64 t; cvta.to.shared.u64 t, %1; cvt.u32.u64 %0, t; }" : "=r"(a) : "l"(p));
    return a;
}
__device__ __forceinline__ void cp16(uint32_t dst, const void* src) {
    asm volatile("cp.async.cg.shared.global [%0], [%1], 16;" :: "r"(dst), "l"(src));
}
__device__ __forceinline__ void cp_commit() { asm volatile("cp.async.commit_group;"); }
__device__ __forceinline__ void cp_wait1() { asm volatile("cp.async.wait_group 1;" ::: "memory"); }
__device__ __forceinline__ void cp_wait0() { asm volatile("cp.async.wait_group 0;" ::: "memory"); }

// ===========================================================================
// K1: p_gen = sigmoid(state_input @ w_pgen + b_pgen); zero row sums.
// ===========================================================================
__global__ void pgen_kernel(const float* __restrict__ state,
                            const float* __restrict__ wp,
                            const float* __restrict__ bp) {
    int row  = blockIdx.x * 8 + (threadIdx.x >> 5);
    int lane = threadIdx.x & 31;
    const float* x = state + (size_t)row * (2 * H_);
    float s = 0.f;
    #pragma unroll 8
    for (int i = lane; i < 2 * H_; i += 32) s += x[i] * wp[i];
    #pragma unroll
    for (int o = 16; o; o >>= 1) s += __shfl_xor_sync(0xffffffffu, s, o);
    if (lane == 0) {
        float z = s + bp[0];
        g_pgen[row]   = 1.f / (1.f + __expf(-z));
        g_rowsum[row] = 0.f;
    }
}

// ===========================================================================
// K2: transpose w2 [H][V] fp32 -> g_w2t [V][H] bf16.
// Tile 64(H) x 32(V); stores are bf16x2 (4B/lane -> 128B/warp transactions).
// ===========================================================================
__global__ void __launch_bounds__(256)
transpose_w2_kernel(const float* __restrict__ w2) {
    __shared__ float tile[64][33];
    int c0 = blockIdx.x * 32;   // vocab base
    int r0 = blockIdx.y * 64;   // H base
    int tid = threadIdx.x;
    int v = tid & 31;
    #pragma unroll
    for (int k = 0; k < 8; k++) {
        int h = (tid >> 5) + k * 8;          // 0..63
        tile[h][v] = w2[(size_t)(r0 + h) * V_ + c0 + v];
    }
    __syncthreads();
    #pragma unroll
    for (int k = 0; k < 4; k++) {
        int sidx = tid + k * 256;            // 0..1023
        int vv = sidx >> 5;                  // 0..31
        int hp = sidx & 31;                  // h-pair 0..31
        __nv_bfloat162 val = __floats2bfloat162_rn(tile[hp * 2][vv], tile[hp * 2 + 1][vv]);
        *(__nv_bfloat162*)&g_w2t[(size_t)(c0 + vv) * H_ + r0 + hp * 2] = val;
    }
}

// ===========================================================================
// K3: hidden = s_output @ w1 + b1  (2048x512x512) -- WMMA bf16, fp32 accum.
// ===========================================================================
#define HLD 72
__global__ void __launch_bounds__(128)
hidden_wmma_kernel(const float* __restrict__ A,
                   const float* __restrict__ W,
                   const float* __restrict__ b1) {
    __shared__ __nv_bfloat16 As[64 * HLD];
    __shared__ __nv_bfloat16 Bs[64 * HLD];
    int tid = threadIdx.x, wid = tid >> 5, lane = tid & 31;
    int warpM = wid >> 1, warpN = wid & 1;
    int m0 = blockIdx.y * 64, n0 = blockIdx.x * 64;

    wmma::fragment<wmma::accumulator, 16, 16, 16, float> c[2][2];
    #pragma unroll
    for (int i = 0; i < 2; i++)
        #pragma unroll
        for (int j = 0; j < 2; j++) wmma::fill_fragment(c[i][j], 0.f);

    for (int kc = 0; kc < 8; kc++) {
        __syncthreads();
        #pragma unroll
        for (int h = 0; h < 8; h++) {
            int idx = tid + h * 128;          // 0..1023 float4 slots
            int r = idx >> 4, c4 = idx & 15;
            float4 v = *(const float4*)&A[(size_t)(m0 + r) * H_ + kc * 64 + c4 * 4];
            __nv_bfloat162* d2 = (__nv_bfloat162*)&As[r * HLD + c4 * 4];
            d2[0] = __floats2bfloat162_rn(v.x, v.y);
            d2[1] = __floats2bfloat162_rn(v.z, v.w);
        }
        #pragma unroll
        for (int h = 0; h < 8; h++) {
            int idx = tid + h * 128;
            int r = idx >> 4, c4 = idx & 15;
            float4 v = *(const float4*)&W[(size_t)(kc * 64 + r) * H_ + n0 + c4 * 4];
            __nv_bfloat162* d2 = (__nv_bfloat162*)&Bs[r * HLD + c4 * 4];
            d2[0] = __floats2bfloat162_rn(v.x, v.y);
            d2[1] = __floats2bfloat162_rn(v.z, v.w);
        }
        __syncthreads();
        #pragma unroll
        for (int kf = 0; kf < 4; kf++) {
            wmma::fragment<wmma::matrix_a, 16, 16, 16, __nv_bfloat16, wmma::row_major> a[2];
            wmma::fragment<wmma::matrix_b, 16, 16, 16, __nv_bfloat16, wmma::row_major> b[2];
            #pragma unroll
            for (int i = 0; i < 2; i++)
                wmma::load_matrix_sync(a[i], As + (warpM * 32 + i * 16) * HLD + kf * 16, HLD);
            #pragma unroll
            for (int j = 0; j < 2; j++)
                wmma::load_matrix_sync(b[j], Bs + (kf * 16) * HLD + warpN * 32 + j * 16, HLD);
            #pragma unroll
            for (int i = 0; i < 2; i++)
                #pragma unroll
                for (int j = 0; j < 2; j++)
                    wmma::mma_sync(c[i][j], a[i], b[j], c[i][j]);
        }
    }
    __syncthreads();
    float* buf = (float*)As + wid * 320;      // 16x20 per-warp staging
    int r = lane >> 1, cbase = (lane & 1) * 8;
    #pragma unroll
    for (int i = 0; i < 2; i++)
        #pragma unroll
        for (int j = 0; j < 2; j++) {
            wmma::store_matrix_sync(buf, c[i][j], 20, wmma::mem_row_major);
            __syncwarp();
            int row = m0 + warpM * 32 + i * 16 + r;
            int col = n0 + warpN * 32 + j * 16 + cbase;
            union { __nv_bfloat162 b2v[4]; uint4 u4; } uu;
            #pragma unroll
            for (int k2 = 0; k2 < 4; k2++)
                uu.b2v[k2] = __floats2bfloat162_rn(
                    buf[r * 20 + cbase + 2 * k2]     + b1[col + 2 * k2],
                    buf[r * 20 + cbase + 2 * k2 + 1] + b1[col + 2 * k2 + 1]);
            *(uint4*)&g_hidden[(size_t)row * H_ + col] = uu.u4;
            __syncwarp();
        }
}

// ===========================================================================
// K4: WMMA GEMM (2048 x 32000 x 512, bf16, fp32 accum) + fused epilogue:
//     l = logit + b2 -> g_logit (fp16, streaming); Z += exp(l) (fp32).
// CTA tile 128x128, BK=64, cp.async double-buffered (measured-best),
// 8 warps (2Mx4N), warp tile 64x32, ld=72 (conflict-free ldmatrix).
// ===========================================================================
#define LDP  72
#define CHB  (128 * LDP * 2)          // 18432 B per tile buffer
#define SM_A 0                        // 2 buffers: A0, A1
#define SM_B (2 * CHB)                // 2 buffers: B0, B1
#define GSMEM (4 * CHB)               // 73728 B

__global__ void __launch_bounds__(256, 2)
logits_wmma_kernel(const float* __restrict__ b2) {
    extern __shared__ char sm[];
    uint32_t sb = smem_u32(sm);
    float* stage = (float*)sm;                   // epilogue reuse of A buffers
    float* rowsum_sm = (float*)(sm + 10240);     // still inside A buffer 0

    int tid = threadIdx.x, wid = tid >> 5, lane = tid & 31;
    int warpM = wid >> 2, warpN = wid & 3;
    int n0 = blockIdx.x * 128, m0 = blockIdx.y * 128;

    wmma::fragment<wmma::accumulator, 16, 16, 16, float> c[4][2];
    #pragma unroll
    for (int i = 0; i < 4; i++)
        #pragma unroll
        for (int j = 0; j < 2; j++) wmma::fill_fragment(c[i][j], 0.f);

    auto load_chunk = [&](int kc, int buf) {
        #pragma unroll
        for (int h = 0; h < 4; h++) {
            int idx = tid + h * 256;             // 0..1023
            int r = idx >> 3, c16 = idx & 7;
            cp16(sb + SM_A + buf * CHB + r * (LDP * 2) + c16 * 16,
                 &g_hidden[(size_t)(m0 + r) * H_ + kc * 64 + c16 * 8]);
        }
        #pragma unroll
        for (int h = 0; h < 4; h++) {
            int idx = tid + h * 256;
            int r = idx >> 3, c16 = idx & 7;
            cp16(sb + SM_B + buf * CHB + r * (LDP * 2) + c16 * 16,
                 &g_w2t[(size_t)(n0 + r) * H_ + kc * 64 + c16 * 8]);
        }
        cp_commit();
    };

    load_chunk(0, 0);
    load_chunk(1, 1);

    const __nv_bfloat16* Asm = (const __nv_bfloat16*)(sm + SM_A);
    const __nv_bfloat16* Bsm = (const __nv_bfloat16*)(sm + SM_B);

    for (int kc = 0; kc < 8; kc++) {
        int buf = kc & 1;
        if (kc == 7) cp_wait0(); else cp_wait1();
        __syncthreads();

        const __nv_bfloat16* Ab = Asm + buf * (CHB / 2);
        const __nv_bfloat16* Bb = Bsm + buf * (CHB / 2);
        #pragma unroll
        for (int kf = 0; kf < 4; kf++) {
            wmma::fragment<wmma::matrix_a, 16, 16, 16, __nv_bfloat16, wmma::row_major> a[4];
            #pragma unroll
            for (int i = 0; i < 4; i++)
                wmma::load_matrix_sync(a[i], Ab + (warpM * 64 + i * 16) * LDP + kf * 16, LDP);
            #pragma unroll
            for (int j = 0; j < 2; j++) {
                wmma::fragment<wmma::matrix_b, 16, 16, 16, __nv_bfloat16, wmma::col_major> bfr;
                wmma::load_matrix_sync(bfr, Bb + (warpN * 32 + j * 16) * LDP + kf * 16, LDP);
                #pragma unroll
                for (int i = 0; i < 4; i++)
                    wmma::mma_sync(c[i][j], a[i], bfr, c[i][j]);
            }
        }
        __syncthreads();
        if (kc + 2 < 8) load_chunk(kc + 2, buf);   // buffer now free
    }

    // ---- epilogue: l = logit + b2 -> fp16 scratch; rowsum Z += exp(l) ----
    __syncthreads();
    if (tid < 128) rowsum_sm[tid] = 0.f;
    __syncthreads();

    float* buf = stage + wid * 320;  // 16x20 staging per warp
    int r = lane >> 1;
    int cbase = (lane & 1) * 8;
    #pragma unroll
    for (int i = 0; i < 4; i++) {
        #pragma unroll
        for (int j = 0; j < 2; j++) {
            wmma::store_matrix_sync(buf, c[i][j], 20, wmma::mem_row_major);
            __syncwarp();
            int lrow = warpM * 64 + i * 16 + r;
            int grow = m0 + lrow;
            int gcol = n0 + warpN * 32 + j * 16 + cbase;
            float s = 0.f;
            union { __half2 h2[4]; uint4 u4; } uu;
            #pragma unroll
            for (int k2 = 0; k2 < 4; k2++) {
                float l0 = buf[r * 20 + cbase + 2 * k2]     + __ldg(&b2[gcol + 2 * k2]);
                float l1 = buf[r * 20 + cbase + 2 * k2 + 1] + __ldg(&b2[gcol + 2 * k2 + 1]);
                s += __expf(l0) + __expf(l1);
                uu.h2[k2] = __floats2half2_rn(l0, l1);
            }
            __stcs((uint4*)&g_logit[(size_t)grow * V_ + gcol], uu.u4);
            s += __shfl_xor_sync(0xffffffffu, s, 1);
            if ((lane & 1) == 0) atomicAdd(&rowsum_sm[lrow], s);
            __syncwarp();
        }
    }
    __syncthreads();
    if (tid < 128) atomicAdd(&g_rowsum[m0 + tid], rowsum_sm[tid]);
}

// ===========================================================================
// K5: single pass. Default: out = l + log(p/Z) (no MUFU). Scattered lanes
// (bitmap-flagged, <=400/row): out = log(p*exp(l)/Z + a + 1e-12).
// ===========================================================================
__device__ __forceinline__ float hash_lookup(int idx, const int* keys, const float* vals) {
    int h = idx & 1023;
    while (keys[h] != idx) h = (h + 1) & 1023;
    return vals[h];
}

__global__ void final_kernel(const float* __restrict__ attn,
                             const int* __restrict__ ebev,
                             float* __restrict__ out) {
    __shared__ unsigned bitmap[1000];   // 32000 bits
    __shared__ int keys[1024];
    __shared__ float vals[1024];
    int row = blockIdx.x;
    int b = row >> 8;                   // T_ = 256
    int tid = threadIdx.x;
    for (int i = tid; i < 1000; i += 256) bitmap[i] = 0u;
    for (int i = tid; i < 1024; i += 256) { keys[i] = -1; vals[i] = 0.f; }
    __syncthreads();
    float p = g_pgen[row];
    float Z = g_rowsum[row];
    float omp = 1.f - p;
    float C  = __logf(p) - __logf(Z);   // log(p/Z)
    float pz = p / Z;

    for (int s = tid; s < S_; s += 256) {
        int idx = ebev[b * S_ + s];
        float v = omp * attn[(size_t)row * S_ + s];
        atomicOr(&bitmap[idx >> 5], 1u << (idx & 31));
        int h = idx & 1023;
        while (true) {
            int old = atomicCAS(&keys[h], -1, idx);
            if (old == -1 || old == idx) { atomicAdd(&vals[h], v); break; }
            h = (h + 1) & 1023;
        }
    }
    __syncthreads();

    const uint4* lrow = (const uint4*)&g_logit[(size_t)row * V_];
    float4* orow = (float4*)&out[(size_t)row * V_];
    for (int q = tid; q < V_ / 8; q += 256) {
        uint4 e8 = __ldcs(&lrow[q]);
        int vbase = q * 8;
        unsigned w = (bitmap[vbase >> 5] >> (vbase & 31)) & 0xFFu;
        const __half2* hp = (const __half2*)&e8;
        float l[8], f[8];
        #pragma unroll
        for (int k = 0; k < 4; k++) {
            float2 fv = __half22float2(hp[k]);
            l[2 * k] = fv.x;  l[2 * k + 1] = fv.y;
        }
        #pragma unroll
        for (int k = 0; k < 8; k++) f[k] = l[k] + C;
        if (w) {
            #pragma unroll
            for (int k = 0; k < 8; k++)
                if (w & (1u << k))
                    f[k] = __logf(pz * __expf(l[k]) +
                                  hash_lookup(vbase + k, keys, vals) + 1e-12f);
        }
        __stcs(&orow[2 * q],     make_float4(f[0], f[1], f[2], f[3]));
        __stcs(&orow[2 * q + 1], make_float4(f[4], f[5], f[6], f[7]));
    }
}

// ===========================================================================
extern "C" void kernel_launch(void* const* d_in, const int* in_sizes, int n_in,
                              void* d_out, int out_size) {
    const float* s_output = (const float*)d_in[0];
    const float* state    = (const float*)d_in[1];
    const float* attn     = (const float*)d_in[2];
    const int*   ebev     = (const int*)d_in[3];
    const float* w_pgen   = (const float*)d_in[4];
    const float* b_pgen   = (const float*)d_in[5];
    const float* w1       = (const float*)d_in[6];
    const float* b1       = (const float*)d_in[7];
    const float* w2       = (const float*)d_in[8];
    const float* b2       = (const float*)d_in[9];
    float* out = (float*)d_out;

    cudaFuncSetAttribute(logits_wmma_kernel,
                         cudaFuncAttributeMaxDynamicSharedMemorySize, GSMEM);

    pgen_kernel<<<R_ / 8, 256>>>(state, w_pgen, b_pgen);
    transpose_w2_kernel<<<dim3(V_ / 32, H_ / 64), 256>>>(w2);
    hidden_wmma_kernel<<<dim3(H_ / 64, R_ / 64), 128>>>(s_output, w1, b1);
    logits_wmma_kernel<<<dim3(V_ / 128, R_ / 128), 256, GSMEM>>>(b2);
    final_kernel<<<R_, 256>>>(attn, ebev, out);
}

// round 15
// speedup vs baseline: 1.1057x; 1.0059x over previous
#include <cuda_runtime.h>
#include <cuda_bf16.h>
#include <cuda_fp16.h>
#include <mma.h>
#include <cstdint>

using namespace nvcuda;

#define B_ 8
#define T_ 256
#define S_ 400
#define H_ 512
#define V_ 32000
#define R_ 2048   // B*T rows

// ---- scratch (no cudaMalloc allowed -> __device__ globals) ----
__device__ __half          g_logit[(size_t)R_ * V_]; // 131 MB: logits+b2 fp16
__device__ __nv_bfloat16   g_w2t[(size_t)V_ * H_];   // 32.8 MB: w2 transposed [V][H] bf16
__device__ __nv_bfloat16   g_hidden[R_ * H_];        // 2 MB: bf16 hidden
__device__ float           g_pgen[R_];
__device__ float           g_rowsum[R_];

// ---- cp.async helpers ----
__device__ __forceinline__ uint32_t smem_u32(const void* p) {
    uint32_t a;
    asm("{ .reg .u64 t; cvta.to.shared.u64 t, %1; cvt.u32.u64 %0, t; }" : "=r"(a) : "l"(p));
    return a;
}
__device__ __forceinline__ void cp16(uint32_t dst, const void* src) {
    asm volatile("cp.async.cg.shared.global [%0], [%1], 16;" :: "r"(dst), "l"(src));
}
__device__ __forceinline__ void cp_commit() { asm volatile("cp.async.commit_group;"); }
__device__ __forceinline__ void cp_wait1() { asm volatile("cp.async.wait_group 1;" ::: "memory"); }
__device__ __forceinline__ void cp_wait0() { asm volatile("cp.async.wait_group 0;" ::: "memory"); }

// ===========================================================================
// K1: p_gen = sigmoid(state_input @ w_pgen + b_pgen); zero row sums.
// ===========================================================================
__global__ void pgen_kernel(const float* __restrict__ state,
                            const float* __restrict__ wp,
                            const float* __restrict__ bp) {
    int row  = blockIdx.x * 8 + (threadIdx.x >> 5);
    int lane = threadIdx.x & 31;
    const float* x = state + (size_t)row * (2 * H_);
    float s = 0.f;
    #pragma unroll 8
    for (int i = lane; i < 2 * H_; i += 32) s += x[i] * wp[i];
    #pragma unroll
    for (int o = 16; o; o >>= 1) s += __shfl_xor_sync(0xffffffffu, s, o);
    if (lane == 0) {
        float z = s + bp[0];
        g_pgen[row]   = 1.f / (1.f + __expf(-z));
        g_rowsum[row] = 0.f;
    }
}

// ===========================================================================
// K2: transpose w2 [H][V] fp32 -> g_w2t [V][H] bf16.
// Tile 64(H) x 32(V); stores are bf16x2 (4B/lane -> 128B/warp transactions).
// ===========================================================================
__global__ void __launch_bounds__(256)
transpose_w2_kernel(const float* __restrict__ w2) {
    __shared__ float tile[64][33];
    int c0 = blockIdx.x * 32;   // vocab base
    int r0 = blockIdx.y * 64;   // H base
    int tid = threadIdx.x;
    int v = tid & 31;
    #pragma unroll
    for (int k = 0; k < 8; k++) {
        int h = (tid >> 5) + k * 8;          // 0..63
        tile[h][v] = __ldcs(&w2[(size_t)(r0 + h) * V_ + c0 + v]);
    }
    __syncthreads();
    #pragma unroll
    for (int k = 0; k < 4; k++) {
        int sidx = tid + k * 256;            // 0..1023
        int vv = sidx >> 5;                  // 0..31
        int hp = sidx & 31;                  // h-pair 0..31
        __nv_bfloat162 val = __floats2bfloat162_rn(tile[hp * 2][vv], tile[hp * 2 + 1][vv]);
        *(__nv_bfloat162*)&g_w2t[(size_t)(c0 + vv) * H_ + r0 + hp * 2] = val;
    }
}

// ===========================================================================
// K3: hidden = s_output @ w1 + b1  (2048x512x512) -- WMMA bf16, fp32 accum.
// ===========================================================================
#define HLD 72
__global__ void __launch_bounds__(128)
hidden_wmma_kernel(const float* __restrict__ A,
                   const float* __restrict__ W,
                   const float* __restrict__ b1) {
    __shared__ __nv_bfloat16 As[64 * HLD];
    __shared__ __nv_bfloat16 Bs[64 * HLD];
    int tid = threadIdx.x, wid = tid >> 5, lane = tid & 31;
    int warpM = wid >> 1, warpN = wid & 1;
    int m0 = blockIdx.y * 64, n0 = blockIdx.x * 64;

    wmma::fragment<wmma::accumulator, 16, 16, 16, float> c[2][2];
    #pragma unroll
    for (int i = 0; i < 2; i++)
        #pragma unroll
        for (int j = 0; j < 2; j++) wmma::fill_fragment(c[i][j], 0.f);

    for (int kc = 0; kc < 8; kc++) {
        __syncthreads();
        #pragma unroll
        for (int h = 0; h < 8; h++) {
            int idx = tid + h * 128;          // 0..1023 float4 slots
            int r = idx >> 4, c4 = idx & 15;
            float4 v = *(const float4*)&A[(size_t)(m0 + r) * H_ + kc * 64 + c4 * 4];
            __nv_bfloat162* d2 = (__nv_bfloat162*)&As[r * HLD + c4 * 4];
            d2[0] = __floats2bfloat162_rn(v.x, v.y);
            d2[1] = __floats2bfloat162_rn(v.z, v.w);
        }
        #pragma unroll
        for (int h = 0; h < 8; h++) {
            int idx = tid + h * 128;
            int r = idx >> 4, c4 = idx & 15;
            float4 v = *(const float4*)&W[(size_t)(kc * 64 + r) * H_ + n0 + c4 * 4];
            __nv_bfloat162* d2 = (__nv_bfloat162*)&Bs[r * HLD + c4 * 4];
            d2[0] = __floats2bfloat162_rn(v.x, v.y);
            d2[1] = __floats2bfloat162_rn(v.z, v.w);
        }
        __syncthreads();
        #pragma unroll
        for (int kf = 0; kf < 4; kf++) {
            wmma::fragment<wmma::matrix_a, 16, 16, 16, __nv_bfloat16, wmma::row_major> a[2];
            wmma::fragment<wmma::matrix_b, 16, 16, 16, __nv_bfloat16, wmma::row_major> b[2];
            #pragma unroll
            for (int i = 0; i < 2; i++)
                wmma::load_matrix_sync(a[i], As + (warpM * 32 + i * 16) * HLD + kf * 16, HLD);
            #pragma unroll
            for (int j = 0; j < 2; j++)
                wmma::load_matrix_sync(b[j], Bs + (kf * 16) * HLD + warpN * 32 + j * 16, HLD);
            #pragma unroll
            for (int i = 0; i < 2; i++)
                #pragma unroll
                for (int j = 0; j < 2; j++)
                    wmma::mma_sync(c[i][j], a[i], b[j], c[i][j]);
        }
    }
    __syncthreads();
    float* buf = (float*)As + wid * 320;      // 16x20 per-warp staging
    int r = lane >> 1, cbase = (lane & 1) * 8;
    #pragma unroll
    for (int i = 0; i < 2; i++)
        #pragma unroll
        for (int j = 0; j < 2; j++) {
            wmma::store_matrix_sync(buf, c[i][j], 20, wmma::mem_row_major);
            __syncwarp();
            int row = m0 + warpM * 32 + i * 16 + r;
            int col = n0 + warpN * 32 + j * 16 + cbase;
            union { __nv_bfloat162 b2v[4]; uint4 u4; } uu;
            #pragma unroll
            for (int k2 = 0; k2 < 4; k2++)
                uu.b2v[k2] = __floats2bfloat162_rn(
                    buf[r * 20 + cbase + 2 * k2]     + b1[col + 2 * k2],
                    buf[r * 20 + cbase + 2 * k2 + 1] + b1[col + 2 * k2 + 1]);
            *(uint4*)&g_hidden[(size_t)row * H_ + col] = uu.u4;
            __syncwarp();
        }
}

// ===========================================================================
// K4: WMMA GEMM (2048 x 32000 x 512, bf16, fp32 accum) + fused epilogue:
//     l = logit + b2 -> g_logit (fp16, streaming); Z += exp(l) (fp32).
// CTA tile 64(M)x128(N), BK=64, cp.async double-buffered, 4 warps (2Mx2N),
// warp tile 32x64 (a[2]+b[4] per kf: 6 LDSM per 8 WMMA). 4 CTAs/SM via
// __launch_bounds__(128,4): 16 warps/SM in 4 independent scheduling
// domains -> barriers sync only 128 threads, latency hidden by CTA overlap.
// ===========================================================================
#define LDP   72
#define ACH   (64 * LDP * 2)           // 9216 B per A stage
#define BCH   (128 * LDP * 2)          // 18432 B per B stage
#define SM_A  0                        // A0, A1
#define SM_B  (2 * ACH)                // B0, B1
#define GSMEM (2 * ACH + 2 * BCH)      // 55296 B

__global__ void __launch_bounds__(128, 4)
logits_wmma_kernel(const float* __restrict__ b2) {
    extern __shared__ char sm[];
    uint32_t sb = smem_u32(sm);
    float* stage = (float*)sm;                   // epilogue reuse of A buffers
    float* rowsum_sm = (float*)(sm + 6144);      // 64 floats, inside A region

    int tid = threadIdx.x, wid = tid >> 5, lane = tid & 31;
    int warpM = wid >> 1, warpN = wid & 1;
    int n0 = blockIdx.x * 128, m0 = blockIdx.y * 64;

    wmma::fragment<wmma::accumulator, 16, 16, 16, float> c[2][4];
    #pragma unroll
    for (int i = 0; i < 2; i++)
        #pragma unroll
        for (int j = 0; j < 4; j++) wmma::fill_fragment(c[i][j], 0.f);

    auto load_chunk = [&](int kc, int buf) {
        #pragma unroll
        for (int h = 0; h < 4; h++) {
            int idx = tid + h * 128;             // 0..511 (64 rows x 8 x16B)
            int r = idx >> 3, c16 = idx & 7;
            cp16(sb + SM_A + buf * ACH + r * (LDP * 2) + c16 * 16,
                 &g_hidden[(size_t)(m0 + r) * H_ + kc * 64 + c16 * 8]);
        }
        #pragma unroll
        for (int h = 0; h < 8; h++) {
            int idx = tid + h * 128;             // 0..1023 (128 rows x 8 x16B)
            int r = idx >> 3, c16 = idx & 7;
            cp16(sb + SM_B + buf * BCH + r * (LDP * 2) + c16 * 16,
                 &g_w2t[(size_t)(n0 + r) * H_ + kc * 64 + c16 * 8]);
        }
        cp_commit();
    };

    load_chunk(0, 0);
    load_chunk(1, 1);

    const __nv_bfloat16* Asm = (const __nv_bfloat16*)(sm + SM_A);
    const __nv_bfloat16* Bsm = (const __nv_bfloat16*)(sm + SM_B);

    for (int kc = 0; kc < 8; kc++) {
        int buf = kc & 1;
        if (kc == 7) cp_wait0(); else cp_wait1();
        __syncthreads();

        const __nv_bfloat16* Ab = Asm + buf * (ACH / 2);
        const __nv_bfloat16* Bb = Bsm + buf * (BCH / 2);
        #pragma unroll
        for (int kf = 0; kf < 4; kf++) {
            wmma::fragment<wmma::matrix_a, 16, 16, 16, __nv_bfloat16, wmma::row_major> a[2];
            #pragma unroll
            for (int i = 0; i < 2; i++)
                wmma::load_matrix_sync(a[i], Ab + (warpM * 32 + i * 16) * LDP + kf * 16, LDP);
            #pragma unroll
            for (int j = 0; j < 4; j++) {
                wmma::fragment<wmma::matrix_b, 16, 16, 16, __nv_bfloat16, wmma::col_major> bfr;
                wmma::load_matrix_sync(bfr, Bb + (warpN * 64 + j * 16) * LDP + kf * 16, LDP);
                #pragma unroll
                for (int i = 0; i < 2; i++)
                    wmma::mma_sync(c[i][j], a[i], bfr, c[i][j]);
            }
        }
        __syncthreads();
        if (kc + 2 < 8) load_chunk(kc + 2, buf);   // buffer now free
    }

    // ---- epilogue: l = logit + b2 -> fp16 scratch; rowsum Z += exp(l) ----
    __syncthreads();
    if (tid < 64) rowsum_sm[tid] = 0.f;
    __syncthreads();

    float* buf = stage + wid * 320;  // 16x20 staging per warp
    int r = lane >> 1;
    int cbase = (lane & 1) * 8;
    #pragma unroll
    for (int i = 0; i < 2; i++) {
        float srow = 0.f;
        #pragma unroll
        for (int j = 0; j < 4; j++) {
            wmma::store_matrix_sync(buf, c[i][j], 20, wmma::mem_row_major);
            __syncwarp();
            int lrow = warpM * 32 + i * 16 + r;
            int grow = m0 + lrow;
            int gcol = n0 + warpN * 64 + j * 16 + cbase;
            float s = 0.f;
            union { __half2 h2[4]; uint4 u4; } uu;
            #pragma unroll
            for (int k2 = 0; k2 < 4; k2++) {
                float l0 = buf[r * 20 + cbase + 2 * k2]     + __ldg(&b2[gcol + 2 * k2]);
                float l1 = buf[r * 20 + cbase + 2 * k2 + 1] + __ldg(&b2[gcol + 2 * k2 + 1]);
                s += __expf(l0) + __expf(l1);
                uu.h2[k2] = __floats2half2_rn(l0, l1);
            }
            __stcs((uint4*)&g_logit[(size_t)grow * V_ + gcol], uu.u4);
            srow += s;
            __syncwarp();
        }
        int lrow = warpM * 32 + i * 16 + r;
        srow += __shfl_xor_sync(0xffffffffu, srow, 1);
        if ((lane & 1) == 0) atomicAdd(&rowsum_sm[lrow], srow);
    }
    __syncthreads();
    if (tid < 64) atomicAdd(&g_rowsum[m0 + tid], rowsum_sm[tid]);
}

// ===========================================================================
// K5: single pass. Default: out = l + log(p/Z) (no MUFU). Scattered lanes
// (bitmap-flagged, <=400/row): out = log(p*exp(l)/Z + a + 1e-12).
// ===========================================================================
__device__ __forceinline__ float hash_lookup(int idx, const int* keys, const float* vals) {
    int h = idx & 1023;
    while (keys[h] != idx) h = (h + 1) & 1023;
    return vals[h];
}

__global__ void final_kernel(const float* __restrict__ attn,
                             const int* __restrict__ ebev,
                             float* __restrict__ out) {
    __shared__ unsigned bitmap[1000];   // 32000 bits
    __shared__ int keys[1024];
    __shared__ float vals[1024];
    int row = blockIdx.x;
    int b = row >> 8;                   // T_ = 256
    int tid = threadIdx.x;
    for (int i = tid; i < 1000; i += 256) bitmap[i] = 0u;
    for (int i = tid; i < 1024; i += 256) { keys[i] = -1; vals[i] = 0.f; }
    __syncthreads();
    float p = g_pgen[row];
    float Z = g_rowsum[row];
    float omp = 1.f - p;
    float C  = __logf(p) - __logf(Z);   // log(p/Z)
    float pz = p / Z;

    for (int s = tid; s < S_; s += 256) {
        int idx = ebev[b * S_ + s];
        float v = omp * attn[(size_t)row * S_ + s];
        atomicOr(&bitmap[idx >> 5], 1u << (idx & 31));
        int h = idx & 1023;
        while (true) {
            int old = atomicCAS(&keys[h], -1, idx);
            if (old == -1 || old == idx) { atomicAdd(&vals[h], v); break; }
            h = (h + 1) & 1023;
        }
    }
    __syncthreads();

    const uint4* lrow = (const uint4*)&g_logit[(size_t)row * V_];
    float4* orow = (float4*)&out[(size_t)row * V_];
    for (int q = tid; q < V_ / 8; q += 256) {
        uint4 e8 = __ldcs(&lrow[q]);
        int vbase = q * 8;
        unsigned w = (bitmap[vbase >> 5] >> (vbase & 31)) & 0xFFu;
        const __half2* hp = (const __half2*)&e8;
        float l[8], f[8];
        #pragma unroll
        for (int k = 0; k < 4; k++) {
            float2 fv = __half22float2(hp[k]);
            l[2 * k] = fv.x;  l[2 * k + 1] = fv.y;
        }
        #pragma unroll
        for (int k = 0; k < 8; k++) f[k] = l[k] + C;
        if (w) {
            #pragma unroll
            for (int k = 0; k < 8; k++)
                if (w & (1u << k))
                    f[k] = __logf(pz * __expf(l[k]) +
                                  hash_lookup(vbase + k, keys, vals) + 1e-12f);
        }
        __stcs(&orow[2 * q],     make_float4(f[0], f[1], f[2], f[3]));
        __stcs(&orow[2 * q + 1], make_float4(f[4], f[5], f[6], f[7]));
    }
}

// ===========================================================================
extern "C" void kernel_launch(void* const* d_in, const int* in_sizes, int n_in,
                              void* d_out, int out_size) {
    const float* s_output = (const float*)d_in[0];
    const float* state    = (const float*)d_in[1];
    const float* attn     = (const float*)d_in[2];
    const int*   ebev     = (const int*)d_in[3];
    const float* w_pgen   = (const float*)d_in[4];
    const float* b_pgen   = (const float*)d_in[5];
    const float* w1       = (const float*)d_in[6];
    const float* b1       = (const float*)d_in[7];
    const float* w2       = (const float*)d_in[8];
    const float* b2       = (const float*)d_in[9];
    float* out = (float*)d_out;

    cudaFuncSetAttribute(logits_wmma_kernel,
                         cudaFuncAttributeMaxDynamicSharedMemorySize, GSMEM);

    pgen_kernel<<<R_ / 8, 256>>>(state, w_pgen, b_pgen);
    transpose_w2_kernel<<<dim3(V_ / 32, H_ / 64), 256>>>(w2);
    hidden_wmma_kernel<<<dim3(H_ / 64, R_ / 64), 128>>>(s_output, w1, b1);
    logits_wmma_kernel<<<dim3(V_ / 128, R_ / 64), 128, GSMEM>>>(b2);
    final_kernel<<<R_, 256>>>(attn, ebev, out);
}